// round 8
// baseline (speedup 1.0000x reference)
#include <cuda_runtime.h>

#define NUSERS 40000
#define NITEMS 16384
#define MAXNNZ 1000000
#define BB 64
#define LAMBDA 500.0f
#define MAX_ITER 30
#define TOL2 1e-12   // TOL^2 vs Rs (sum of squares)

#define PBLOCKS 296                   // 148 SMs x 2 blocks of 512 threads
#define PTHREADS (PBLOCKS * 512)      // 151552
#define PWARPS   (PTHREADS / 32)      // 4736
#define NELEM    (NITEMS * BB)        // 1048576
#define ELPT     7                    // 151552*7 >= NELEM

// ---------------- device global scratch ----------------
__device__ int    g_row_cnt[NUSERS];
__device__ int    g_row_ptr[NUSERS + 1];
__device__ int    g_row_off[NUSERS];
__device__ int    g_col_cnt[NITEMS];
__device__ int    g_col_ptr[NITEMS + 1];
__device__ int    g_col_off[NITEMS];
__device__ __align__(16) int2 g_csr[MAXNNZ];   // {col, float_bits(val)}
__device__ __align__(16) int2 g_csc[MAXNNZ];   // {row, float_bits(val)}
__device__ int    g_bsum[64];

__device__ float  g_tmp[NUSERS * BB];
__device__ float  g_Xt [NELEM];
__device__ float  g_X  [NELEM];
__device__ float  g_R  [NELEM];
__device__ float  g_P  [NELEM];
__device__ float  g_AP [NELEM];

__device__ double g_RsA[BB];   // Rs_old
__device__ double g_RsB[BB];   // Rs_new
__device__ double g_pAP[BB];
__device__ int    g_done;

// ---------------- grid-wide barrier (sense via generation counter) ----------------
__device__ unsigned g_bar_cnt;
__device__ unsigned g_bar_gen;

__device__ __forceinline__ void grid_barrier(unsigned nblocks) {
    __syncthreads();
    if (threadIdx.x == 0) {
        unsigned gen = *(volatile unsigned*)&g_bar_gen;
        __threadfence();
        if (atomicAdd(&g_bar_cnt, 1u) == nblocks - 1u) {
            g_bar_cnt = 0u;
            __threadfence();
            atomicAdd(&g_bar_gen, 1u);
        } else {
            while (*(volatile unsigned*)&g_bar_gen == gen) { }
        }
        __threadfence();
    }
    __syncthreads();
}

// ---------------- software-pipelined 8-wide row gather ----------------
// 8 gathers in flight + next group's idx prefetched before current FMAs.
__device__ __forceinline__ float2 row_gather(const int2* __restrict__ idx,
                                             const float* __restrict__ V,
                                             int s, int e, int lane) {
    float2 a0 = {0.f,0.f}, a1 = {0.f,0.f}, a2 = {0.f,0.f}, a3 = {0.f,0.f};
    int j = s;
    if ((j & 1) && j < e) {                       // parity peel -> 16B alignment
        int2 p = __ldcs(idx + j);
        float2 q = *(const float2*)(V + p.x * BB + 2 * lane);
        float v = __int_as_float(p.y);
        a0.x += v * q.x; a0.y += v * q.y;
        j++;
    }

    // ---- 8-wide pipelined main loop ----
    int4 A, B, C, D;
    bool run = (j + 7 < e);
    if (run) {
        A = __ldcs((const int4*)(idx + j));
        B = __ldcs((const int4*)(idx + j + 2));
        C = __ldcs((const int4*)(idx + j + 4));
        D = __ldcs((const int4*)(idx + j + 6));
    }
    while (run) {
        int jn = j + 8;
        bool next = (jn + 7 < e);
        int4 An, Bn, Cn, Dn;
        if (next) {                               // prefetch next group's indices
            An = __ldcs((const int4*)(idx + jn));
            Bn = __ldcs((const int4*)(idx + jn + 2));
            Cn = __ldcs((const int4*)(idx + jn + 4));
            Dn = __ldcs((const int4*)(idx + jn + 6));
        }
        float2 q0 = *(const float2*)(V + A.x * BB + 2 * lane);
        float2 q1 = *(const float2*)(V + A.z * BB + 2 * lane);
        float2 q2 = *(const float2*)(V + B.x * BB + 2 * lane);
        float2 q3 = *(const float2*)(V + B.z * BB + 2 * lane);
        float2 q4 = *(const float2*)(V + C.x * BB + 2 * lane);
        float2 q5 = *(const float2*)(V + C.z * BB + 2 * lane);
        float2 q6 = *(const float2*)(V + D.x * BB + 2 * lane);
        float2 q7 = *(const float2*)(V + D.z * BB + 2 * lane);
        float v0 = __int_as_float(A.y), v1 = __int_as_float(A.w);
        float v2 = __int_as_float(B.y), v3 = __int_as_float(B.w);
        float v4 = __int_as_float(C.y), v5 = __int_as_float(C.w);
        float v6 = __int_as_float(D.y), v7 = __int_as_float(D.w);
        a0.x += v0*q0.x; a0.y += v0*q0.y;
        a1.x += v1*q1.x; a1.y += v1*q1.y;
        a2.x += v2*q2.x; a2.y += v2*q2.y;
        a3.x += v3*q3.x; a3.y += v3*q3.y;
        a0.x += v4*q4.x; a0.y += v4*q4.y;
        a1.x += v5*q5.x; a1.y += v5*q5.y;
        a2.x += v6*q6.x; a2.y += v6*q6.y;
        a3.x += v7*q7.x; a3.y += v7*q7.y;
        A = An; B = Bn; C = Cn; D = Dn;
        j = jn; run = next;
    }

    // ---- tail: 4-wide, 2-wide, scalar ----
    if (j + 3 < e) {
        int4 A1 = __ldcs((const int4*)(idx + j));
        int4 B1 = __ldcs((const int4*)(idx + j + 2));
        float2 q0 = *(const float2*)(V + A1.x * BB + 2 * lane);
        float2 q1 = *(const float2*)(V + A1.z * BB + 2 * lane);
        float2 q2 = *(const float2*)(V + B1.x * BB + 2 * lane);
        float2 q3 = *(const float2*)(V + B1.z * BB + 2 * lane);
        float v0 = __int_as_float(A1.y), v1 = __int_as_float(A1.w);
        float v2 = __int_as_float(B1.y), v3 = __int_as_float(B1.w);
        a0.x += v0*q0.x; a0.y += v0*q0.y;
        a1.x += v1*q1.x; a1.y += v1*q1.y;
        a2.x += v2*q2.x; a2.y += v2*q2.y;
        a3.x += v3*q3.x; a3.y += v3*q3.y;
        j += 4;
    }
    if (j + 1 < e) {
        int4 A1 = __ldcs((const int4*)(idx + j));
        float2 q0 = *(const float2*)(V + A1.x * BB + 2 * lane);
        float2 q1 = *(const float2*)(V + A1.z * BB + 2 * lane);
        float v0 = __int_as_float(A1.y), v1 = __int_as_float(A1.w);
        a0.x += v0*q0.x; a0.y += v0*q0.y;
        a1.x += v1*q1.x; a1.y += v1*q1.y;
        j += 2;
    }
    if (j < e) {
        int2 p = __ldcs(idx + j);
        float2 q = *(const float2*)(V + p.x * BB + 2 * lane);
        float v = __int_as_float(p.y);
        a0.x += v*q.x; a0.y += v*q.y;
    }
    return make_float2((a0.x + a1.x) + (a2.x + a3.x),
                       (a0.y + a1.y) + (a2.y + a3.y));
}

// ---------------- k_pre: tiled transpose + X zero + histogram + scalar zero ----------------
__global__ void k_pre(const float* __restrict__ Xb, const int* __restrict__ rows,
                      const int* __restrict__ cols, int nnz) {
    int b = blockIdx.x;
    if (b < 1024) {
        __shared__ float tile[32][33];
        int itile = (b & 511) * 32;
        int btile = (b >> 9) * 32;
        int tx = threadIdx.x & 31;
        int ty = threadIdx.x >> 5;               // 0..7
        #pragma unroll
        for (int r = 0; r < 32; r += 8)          // coalesced read along item
            tile[ty + r][tx] = __ldg(&Xb[(btile + ty + r) * NITEMS + itile + tx]);
        __syncthreads();
        #pragma unroll
        for (int r = 0; r < 32; r += 8) {
            int item = itile + ty + r;
            g_Xt[item * BB + btile + tx] = tile[tx][ty + r];
            g_X [item * BB + btile + tx] = 0.0f;
        }
        if (b == 0) {
            if (threadIdx.x < BB) {
                g_RsA[threadIdx.x] = 0.0; g_RsB[threadIdx.x] = 0.0;
                g_pAP[threadIdx.x] = 0.0;
            }
            if (threadIdx.x == 64) g_done = 0;
        }
    } else {
        int k2 = ((b - 1024) * 256 + threadIdx.x) * 2;
        if (k2 + 1 < nnz) {
            int2 r = *(const int2*)(rows + k2);
            int2 c = *(const int2*)(cols + k2);
            atomicAdd(&g_row_cnt[r.x], 1); atomicAdd(&g_row_cnt[r.y], 1);
            atomicAdd(&g_col_cnt[c.x], 1); atomicAdd(&g_col_cnt[c.y], 1);
        } else {
            for (int k = k2; k < nnz; k++) {
                atomicAdd(&g_row_cnt[__ldg(rows + k)], 1);
                atomicAdd(&g_col_cnt[__ldg(cols + k)], 1);
            }
        }
    }
}

// ---------------- fused hierarchical scan (56 resident blocks), self-cleaning ----------------
__global__ void k_scan() {
    __shared__ int wsum[32];
    int b = blockIdx.x;
    bool isRow = (b < 40);
    int* cnt = isRow ? g_row_cnt : g_col_cnt;
    int* ptr = isRow ? g_row_ptr : g_col_ptr;
    int* off = isRow ? g_row_off : g_col_off;
    int n    = isRow ? NUSERS    : NITEMS;
    int i = (isRow ? b : (b - 40)) * 1024 + threadIdx.x;
    int lane = threadIdx.x & 31, w = threadIdx.x >> 5;

    int v = 0;
    if (i < n) { v = cnt[i]; cnt[i] = 0; }   // consume + clean for next replay
    int x = v;
    #pragma unroll
    for (int s = 1; s < 32; s <<= 1) {
        int t = __shfl_up_sync(0xffffffffu, x, s);
        if (lane >= s) x += t;
    }
    if (lane == 31) wsum[w] = x;
    __syncthreads();
    if (w == 0) {
        int y = wsum[lane];
        #pragma unroll
        for (int s = 1; s < 32; s <<= 1) {
            int t = __shfl_up_sync(0xffffffffu, y, s);
            if (lane >= s) y += t;
        }
        wsum[lane] = y;
    }
    __syncthreads();
    int incl = x + (w ? wsum[w - 1] : 0);
    int loc_excl = incl - v;
    if (threadIdx.x == 1023) g_bsum[b] = incl;

    grid_barrier(56);

    if (b == 0 && threadIdx.x == 0) {
        int s = 0;
        for (int k = 0; k < 40; k++) { int t = g_bsum[k]; g_bsum[k] = s; s += t; }
        g_row_ptr[NUSERS] = s;
    }
    if (b == 1 && threadIdx.x == 0) {
        int s = 0;
        for (int k = 40; k < 56; k++) { int t = g_bsum[k]; g_bsum[k] = s; s += t; }
        g_col_ptr[NITEMS] = s;
    }

    grid_barrier(56);

    if (i < n) {
        int p = loc_excl + g_bsum[b];
        ptr[i] = p;
        off[i] = p;
    }
}

// ---------------- scatter: 2 nnz per thread, full-width grid ----------------
__global__ void k_scatter(const int* __restrict__ rows, const int* __restrict__ cols,
                          const float* __restrict__ vals, int nnz) {
    int k2 = (blockIdx.x * blockDim.x + threadIdx.x) * 2;
    if (k2 + 1 < nnz) {
        int2   r = *(const int2*)(rows + k2);
        int2   c = *(const int2*)(cols + k2);
        float2 v = *(const float2*)(vals + k2);
        int p0 = atomicAdd(&g_row_off[r.x], 1);
        int p1 = atomicAdd(&g_row_off[r.y], 1);
        g_csr[p0] = make_int2(c.x, __float_as_int(v.x));
        g_csr[p1] = make_int2(c.y, __float_as_int(v.y));
        int q0 = atomicAdd(&g_col_off[c.x], 1);
        int q1 = atomicAdd(&g_col_off[c.y], 1);
        g_csc[q0] = make_int2(r.x, __float_as_int(v.x));
        g_csc[q1] = make_int2(r.y, __float_as_int(v.y));
    } else {
        for (int k = k2; k < nnz; k++) {
            int rr = __ldg(rows + k); int cc = __ldg(cols + k);
            int vb = __float_as_int(__ldg(vals + k));
            int p = atomicAdd(&g_row_off[rr], 1);
            g_csr[p] = make_int2(cc, vb);
            int q = atomicAdd(&g_col_off[cc], 1);
            g_csc[q] = make_int2(rr, vb);
        }
    }
}

// ---------------- persistent CG mega-kernel ----------------
__global__ void __launch_bounds__(512, 2) k_cg(float* __restrict__ out) {
    __shared__ float sd[BB];
    __shared__ float s_a[BB];        // alpha, then beta
    __shared__ float s_rsold[BB];

    int tid  = threadIdx.x;
    int gt   = blockIdx.x * 512 + tid;
    int gw   = gt >> 5;
    int lane = tid & 31;
    int c0   = 2 * lane;
    int c    = tid & 63;   // PTHREADS % 64 == 0 -> column fixed per thread

    // ===== RHS csr: tmp = X @ Xt =====
    for (int row = gw; row < NUSERS; row += PWARPS) {
        float2 o = row_gather(g_csr, g_Xt, g_row_ptr[row], g_row_ptr[row + 1], lane);
        *(float2*)(g_tmp + row * BB + c0) = o;
    }
    grid_barrier(PBLOCKS);

    // ===== RHS csc: R0 = P0 = X^T tmp ; RsA = ||R0||^2 =====
    if (tid < BB) sd[tid] = 0.f;
    __syncthreads();
    {
        float ax = 0.f, ay = 0.f;
        for (int row = gw; row < NITEMS; row += PWARPS) {
            float2 o = row_gather(g_csc, g_tmp, g_col_ptr[row], g_col_ptr[row + 1], lane);
            *(float2*)(g_R + row * BB + c0) = o;
            *(float2*)(g_P + row * BB + c0) = o;
            ax += o.x * o.x; ay += o.y * o.y;
        }
        atomicAdd(&sd[c0], ax); atomicAdd(&sd[c0 + 1], ay);
        __syncthreads();
        if (tid < BB) atomicAdd(&g_RsA[tid], (double)sd[tid]);
    }
    grid_barrier(PBLOCKS);

    // ===== 30 CG iterations (proven core: 4 barriers, explicit RsB reduction) =====
    for (int it = 0; it < MAX_ITER; it++) {
        // ---- csr: tmp = X @ P ; block0 zeroes RsB for this iter
        if (blockIdx.x == 0 && tid < BB) g_RsB[tid] = 0.0;
        for (int row = gw; row < NUSERS; row += PWARPS) {
            float2 o = row_gather(g_csr, g_P, g_row_ptr[row], g_row_ptr[row + 1], lane);
            *(float2*)(g_tmp + row * BB + c0) = o;
        }
        grid_barrier(PBLOCKS);

        // ---- csc: AP = X^T tmp + lambda P ; pAP += P.AP
        if (tid < BB) sd[tid] = 0.f;
        __syncthreads();
        {
            float ax = 0.f, ay = 0.f;
            for (int row = gw; row < NITEMS; row += PWARPS) {
                float2 o = row_gather(g_csc, g_tmp, g_col_ptr[row], g_col_ptr[row + 1], lane);
                float2 p = *(const float2*)(g_P + row * BB + c0);
                o.x += LAMBDA * p.x; o.y += LAMBDA * p.y;
                *(float2*)(g_AP + row * BB + c0) = o;
                ax += p.x * o.x; ay += p.y * o.y;
            }
            atomicAdd(&sd[c0], ax); atomicAdd(&sd[c0 + 1], ay);
            __syncthreads();
            if (tid < BB) atomicAdd(&g_pAP[tid], (double)sd[tid]);
        }
        grid_barrier(PBLOCKS);

        // ---- update1: alpha; X += aP; R -= a AP; RsB = sum(R^2)
        float rc[ELPT], pc[ELPT];
        {
            if (tid < BB) {
                float rso = (float)g_RsA[tid];
                s_a[tid] = rso / ((float)g_pAP[tid] + 1e-12f);
                s_rsold[tid] = rso;
                sd[tid] = 0.f;
            }
            __syncthreads();
            float alpha = s_a[c];
            float acc = 0.f;
            #pragma unroll
            for (int k = 0; k < ELPT; k++) {
                int i = gt + k * PTHREADS;
                if (i < NELEM) {
                    float p = g_P[i], ap = g_AP[i];
                    g_X[i] += alpha * p;
                    float r = g_R[i] - alpha * ap;
                    g_R[i] = r;
                    rc[k] = r; pc[k] = p;
                    acc += r * r;
                }
            }
            atomicAdd(&sd[c], acc);
            __syncthreads();
            if (tid < BB) atomicAdd(&g_RsB[tid], (double)sd[tid]);
        }
        grid_barrier(PBLOCKS);

        // ---- update2: beta; P = R + beta P; rotate scalars in block0
        {
            if (tid < BB) {
                double rsn = g_RsB[tid];
                s_a[tid] = (float)rsn / (s_rsold[tid] + 1e-12f);
                if (blockIdx.x == 0) {       // safe: nobody reads RsA/pAP this phase
                    g_RsA[tid] = rsn;
                    g_pAP[tid] = 0.0;
                }
            }
            __syncthreads();
            float beta = s_a[c];
            #pragma unroll
            for (int k = 0; k < ELPT; k++) {
                int i = gt + k * PTHREADS;
                if (i < NELEM) g_P[i] = rc[k] + beta * pc[k];
            }
            if (blockIdx.x == 0 && tid == 0) {
                int ok = 1;
                for (int q = 0; q < BB; q++)
                    if (g_RsB[q] >= TOL2) { ok = 0; break; }
                if (ok) g_done = 1;
            }
        }
        grid_barrier(PBLOCKS);
        if (*(volatile int*)&g_done) break;   // uniform across all blocks
    }

    // ===== epilogue: tiled transpose g_X (items x 64) -> out (64 x items) =====
    __shared__ float tile[32][65];
    for (int t = blockIdx.x; t < 512; t += PBLOCKS) {
        int it0 = t * 32;
        #pragma unroll
        for (int s = 0; s < 4; s++)
            tile[s * 8 + (tid >> 6)][tid & 63] =
                g_X[(it0 + s * 8 + (tid >> 6)) * BB + (tid & 63)];
        __syncthreads();
        #pragma unroll
        for (int s = 0; s < 4; s++)
            out[(s * 16 + (tid >> 5)) * NITEMS + it0 + (tid & 31)] =
                tile[tid & 31][s * 16 + (tid >> 5)];
        __syncthreads();
    }
}

// ---------------- launch: 4 graph nodes total ----------------
extern "C" void kernel_launch(void* const* d_in, const int* in_sizes, int n_in,
                              void* d_out, int out_size) {
    const float* Xb   = (const float*)d_in[0];
    const int*   rows = (const int*)d_in[1];
    const int*   cols = (const int*)d_in[2];
    const float* vals = (const float*)d_in[3];
    int nnz = in_sizes[1];
    if (nnz > MAXNNZ) nnz = MAXNNZ;

    const int HIST_BLOCKS = (nnz + 511) / 512;            // 2 nnz/thread
    const int PRE_BLOCKS  = 1024 + HIST_BLOCKS;

    k_pre    <<<PRE_BLOCKS, 256>>>(Xb, rows, cols, nnz);
    k_scan   <<<56, 1024>>>();
    k_scatter<<<HIST_BLOCKS, 256>>>(rows, cols, vals, nnz);
    k_cg     <<<PBLOCKS, 512>>>((float*)d_out);
}

// round 10
// speedup vs baseline: 1.9190x; 1.9190x over previous
#include <cuda_runtime.h>

#define NUSERS 40000
#define NITEMS 16384
#define MAXNNZ 1000000
#define BB 64
#define LAMBDA 500.0f
#define MAX_ITER 30
#define TOL2 1e-12   // TOL^2 vs Rs (sum of squares)

#define PBLOCKS 444                   // 148 SMs x 3 blocks of 512 threads
#define PTHREADS (PBLOCKS * 512)      // 227328
#define PWARPS   (PTHREADS / 32)      // 7104
#define NELEM    (NITEMS * BB)        // 1048576

// ---------------- device global scratch ----------------
__device__ int    g_row_cnt[NUSERS];
__device__ int    g_row_ptr[NUSERS + 1];
__device__ int    g_row_off[NUSERS];
__device__ int    g_col_cnt[NITEMS];
__device__ int    g_col_ptr[NITEMS + 1];
__device__ int    g_col_off[NITEMS];
__device__ __align__(16) int2 g_csr[MAXNNZ];   // {col, float_bits(val)}
__device__ __align__(16) int2 g_csc[MAXNNZ];   // {row, float_bits(val)}
__device__ int    g_bsum[64];

__device__ float  g_tmp[NUSERS * BB];
__device__ float  g_Xt [NELEM];
__device__ float  g_X  [NELEM];
__device__ float  g_R  [NELEM];
__device__ float  g_P  [NELEM];
__device__ float  g_AP [NELEM];

__device__ double g_RsA[BB];   // Rs_old
__device__ double g_RsB[BB];   // Rs_new
__device__ double g_pAP[BB];
__device__ int    g_done;

// ---------------- grid-wide barrier (sense via generation counter) ----------------
__device__ unsigned g_bar_cnt;
__device__ unsigned g_bar_gen;

__device__ __forceinline__ void grid_barrier(unsigned nblocks) {
    __syncthreads();
    if (threadIdx.x == 0) {
        unsigned gen = *(volatile unsigned*)&g_bar_gen;
        __threadfence();
        if (atomicAdd(&g_bar_cnt, 1u) == nblocks - 1u) {
            g_bar_cnt = 0u;
            __threadfence();
            atomicAdd(&g_bar_gen, 1u);
        } else {
            while (*(volatile unsigned*)&g_bar_gen == gen) { }
        }
        __threadfence();
    }
    __syncthreads();
}

// ---------------- row gather with cooperative smem idx staging ----------------
// Per 32-nnz chunk: lanes cooperatively LDG one int2 each (2 wavefronts for 32 nnz,
// vs 16 broadcast wavefronts before), stage to smem, inner loop reads via LDS
// broadcast (smem pipe, off the L1 wavefront queue). Inner unroll 4 (reg budget).
__device__ __forceinline__ float2 row_gather(const int2* __restrict__ idx,
                                             const float* __restrict__ V,
                                             int s, int e, int lane,
                                             int2* __restrict__ sbuf) {
    float2 a0 = {0.f,0.f}, a1 = {0.f,0.f}, a2 = {0.f,0.f}, a3 = {0.f,0.f};
    for (int base = s; base < e; base += 32) {
        int n = e - base; if (n > 32) n = 32;
        if (lane < n) sbuf[lane] = __ldcs(idx + base + lane);
        __syncwarp();
        int k = 0;
        for (; k + 3 < n; k += 4) {
            int2 p0 = sbuf[k],     p1 = sbuf[k + 1];
            int2 p2 = sbuf[k + 2], p3 = sbuf[k + 3];
            float2 q0 = *(const float2*)(V + p0.x * BB + 2 * lane);
            float2 q1 = *(const float2*)(V + p1.x * BB + 2 * lane);
            float2 q2 = *(const float2*)(V + p2.x * BB + 2 * lane);
            float2 q3 = *(const float2*)(V + p3.x * BB + 2 * lane);
            float v0 = __int_as_float(p0.y), v1 = __int_as_float(p1.y);
            float v2 = __int_as_float(p2.y), v3 = __int_as_float(p3.y);
            a0.x += v0*q0.x; a0.y += v0*q0.y;
            a1.x += v1*q1.x; a1.y += v1*q1.y;
            a2.x += v2*q2.x; a2.y += v2*q2.y;
            a3.x += v3*q3.x; a3.y += v3*q3.y;
        }
        for (; k < n; k++) {
            int2 p = sbuf[k];
            float2 q = *(const float2*)(V + p.x * BB + 2 * lane);
            float v = __int_as_float(p.y);
            a0.x += v*q.x; a0.y += v*q.y;
        }
        __syncwarp();
    }
    return make_float2((a0.x + a1.x) + (a2.x + a3.x),
                       (a0.y + a1.y) + (a2.y + a3.y));
}

// ---------------- k_pre: tiled transpose + X zero + histogram + scalar zero ----------------
__global__ void k_pre(const float* __restrict__ Xb, const int* __restrict__ rows,
                      const int* __restrict__ cols, int nnz) {
    int b = blockIdx.x;
    if (b < 1024) {
        __shared__ float tile[32][33];
        int itile = (b & 511) * 32;
        int btile = (b >> 9) * 32;
        int tx = threadIdx.x & 31;
        int ty = threadIdx.x >> 5;               // 0..7
        #pragma unroll
        for (int r = 0; r < 32; r += 8)          // coalesced read along item
            tile[ty + r][tx] = __ldg(&Xb[(btile + ty + r) * NITEMS + itile + tx]);
        __syncthreads();
        #pragma unroll
        for (int r = 0; r < 32; r += 8) {
            int item = itile + ty + r;
            g_Xt[item * BB + btile + tx] = tile[tx][ty + r];
            g_X [item * BB + btile + tx] = 0.0f;
        }
        if (b == 0) {
            if (threadIdx.x < BB) {
                g_RsA[threadIdx.x] = 0.0; g_RsB[threadIdx.x] = 0.0;
                g_pAP[threadIdx.x] = 0.0;
            }
            if (threadIdx.x == 64) g_done = 0;
        }
    } else {
        int k2 = ((b - 1024) * 256 + threadIdx.x) * 2;
        if (k2 + 1 < nnz) {
            int2 r = *(const int2*)(rows + k2);
            int2 c = *(const int2*)(cols + k2);
            atomicAdd(&g_row_cnt[r.x], 1); atomicAdd(&g_row_cnt[r.y], 1);
            atomicAdd(&g_col_cnt[c.x], 1); atomicAdd(&g_col_cnt[c.y], 1);
        } else {
            for (int k = k2; k < nnz; k++) {
                atomicAdd(&g_row_cnt[__ldg(rows + k)], 1);
                atomicAdd(&g_col_cnt[__ldg(cols + k)], 1);
            }
        }
    }
}

// ---------------- fused hierarchical scan (56 resident blocks), self-cleaning ----------------
__global__ void k_scan() {
    __shared__ int wsum[32];
    int b = blockIdx.x;
    bool isRow = (b < 40);
    int* cnt = isRow ? g_row_cnt : g_col_cnt;
    int* ptr = isRow ? g_row_ptr : g_col_ptr;
    int* off = isRow ? g_row_off : g_col_off;
    int n    = isRow ? NUSERS    : NITEMS;
    int i = (isRow ? b : (b - 40)) * 1024 + threadIdx.x;
    int lane = threadIdx.x & 31, w = threadIdx.x >> 5;

    int v = 0;
    if (i < n) { v = cnt[i]; cnt[i] = 0; }   // consume + clean for next replay
    int x = v;
    #pragma unroll
    for (int s = 1; s < 32; s <<= 1) {
        int t = __shfl_up_sync(0xffffffffu, x, s);
        if (lane >= s) x += t;
    }
    if (lane == 31) wsum[w] = x;
    __syncthreads();
    if (w == 0) {
        int y = wsum[lane];
        #pragma unroll
        for (int s = 1; s < 32; s <<= 1) {
            int t = __shfl_up_sync(0xffffffffu, y, s);
            if (lane >= s) y += t;
        }
        wsum[lane] = y;
    }
    __syncthreads();
    int incl = x + (w ? wsum[w - 1] : 0);
    int loc_excl = incl - v;
    if (threadIdx.x == 1023) g_bsum[b] = incl;

    grid_barrier(56);

    if (b == 0 && threadIdx.x == 0) {
        int s = 0;
        for (int k = 0; k < 40; k++) { int t = g_bsum[k]; g_bsum[k] = s; s += t; }
        g_row_ptr[NUSERS] = s;
    }
    if (b == 1 && threadIdx.x == 0) {
        int s = 0;
        for (int k = 40; k < 56; k++) { int t = g_bsum[k]; g_bsum[k] = s; s += t; }
        g_col_ptr[NITEMS] = s;
    }

    grid_barrier(56);

    if (i < n) {
        int p = loc_excl + g_bsum[b];
        ptr[i] = p;
        off[i] = p;
    }
}

// ---------------- scatter: 2 nnz per thread, full-width grid ----------------
__global__ void k_scatter(const int* __restrict__ rows, const int* __restrict__ cols,
                          const float* __restrict__ vals, int nnz) {
    int k2 = (blockIdx.x * blockDim.x + threadIdx.x) * 2;
    if (k2 + 1 < nnz) {
        int2   r = *(const int2*)(rows + k2);
        int2   c = *(const int2*)(cols + k2);
        float2 v = *(const float2*)(vals + k2);
        int p0 = atomicAdd(&g_row_off[r.x], 1);
        int p1 = atomicAdd(&g_row_off[r.y], 1);
        g_csr[p0] = make_int2(c.x, __float_as_int(v.x));
        g_csr[p1] = make_int2(c.y, __float_as_int(v.y));
        int q0 = atomicAdd(&g_col_off[c.x], 1);
        int q1 = atomicAdd(&g_col_off[c.y], 1);
        g_csc[q0] = make_int2(r.x, __float_as_int(v.x));
        g_csc[q1] = make_int2(r.y, __float_as_int(v.y));
    } else {
        for (int k = k2; k < nnz; k++) {
            int rr = __ldg(rows + k); int cc = __ldg(cols + k);
            int vb = __float_as_int(__ldg(vals + k));
            int p = atomicAdd(&g_row_off[rr], 1);
            g_csr[p] = make_int2(cc, vb);
            int q = atomicAdd(&g_col_off[cc], 1);
            g_csc[q] = make_int2(rr, vb);
        }
    }
}

// ---------------- persistent CG mega-kernel (R7-proven core; staged-idx gather) ----------------
__global__ void __launch_bounds__(512, 3) k_cg(float* __restrict__ out) {
    __shared__ float sd[BB];
    __shared__ float s_a[BB];        // alpha, then beta
    __shared__ float s_rsold[BB];
    __shared__ int2  s_idx[16][32];  // per-warp idx staging (4KB)

    int tid  = threadIdx.x;
    int gt   = blockIdx.x * 512 + tid;
    int gw   = gt >> 5;
    int lane = tid & 31;
    int c0   = 2 * lane;
    int c    = tid & 63;   // PTHREADS % 64 == 0 -> column fixed per thread
    int2* sbuf = s_idx[tid >> 5];

    // ===== RHS csr: tmp = X @ Xt =====
    for (int row = gw; row < NUSERS; row += PWARPS) {
        float2 o = row_gather(g_csr, g_Xt, g_row_ptr[row], g_row_ptr[row + 1], lane, sbuf);
        *(float2*)(g_tmp + row * BB + c0) = o;
    }
    grid_barrier(PBLOCKS);

    // ===== RHS csc: R0 = P0 = X^T tmp ; RsA = ||R0||^2 =====
    if (tid < BB) sd[tid] = 0.f;
    __syncthreads();
    {
        float ax = 0.f, ay = 0.f;
        for (int row = gw; row < NITEMS; row += PWARPS) {
            float2 o = row_gather(g_csc, g_tmp, g_col_ptr[row], g_col_ptr[row + 1], lane, sbuf);
            *(float2*)(g_R + row * BB + c0) = o;
            *(float2*)(g_P + row * BB + c0) = o;
            ax += o.x * o.x; ay += o.y * o.y;
        }
        atomicAdd(&sd[c0], ax); atomicAdd(&sd[c0 + 1], ay);
        __syncthreads();
        if (tid < BB) atomicAdd(&g_RsA[tid], (double)sd[tid]);
    }
    grid_barrier(PBLOCKS);

    // ===== 30 CG iterations (proven core: 4 barriers, explicit RsB reduction) =====
    for (int it = 0; it < MAX_ITER; it++) {
        // ---- csr: tmp = X @ P ; block0 zeroes RsB for this iter
        if (blockIdx.x == 0 && tid < BB) g_RsB[tid] = 0.0;
        for (int row = gw; row < NUSERS; row += PWARPS) {
            float2 o = row_gather(g_csr, g_P, g_row_ptr[row], g_row_ptr[row + 1], lane, sbuf);
            *(float2*)(g_tmp + row * BB + c0) = o;
        }
        grid_barrier(PBLOCKS);

        // ---- csc: AP = X^T tmp + lambda P ; pAP += P.AP
        if (tid < BB) sd[tid] = 0.f;
        __syncthreads();
        {
            float ax = 0.f, ay = 0.f;
            for (int row = gw; row < NITEMS; row += PWARPS) {
                float2 o = row_gather(g_csc, g_tmp, g_col_ptr[row], g_col_ptr[row + 1], lane, sbuf);
                float2 p = *(const float2*)(g_P + row * BB + c0);
                o.x += LAMBDA * p.x; o.y += LAMBDA * p.y;
                *(float2*)(g_AP + row * BB + c0) = o;
                ax += p.x * o.x; ay += p.y * o.y;
            }
            atomicAdd(&sd[c0], ax); atomicAdd(&sd[c0 + 1], ay);
            __syncthreads();
            if (tid < BB) atomicAdd(&g_pAP[tid], (double)sd[tid]);
        }
        grid_barrier(PBLOCKS);

        // ---- update1: alpha; X += aP; R -= a AP; RsB = sum(R^2)
        float rc[5], pc[5];
        {
            if (tid < BB) {
                float rso = (float)g_RsA[tid];
                s_a[tid] = rso / ((float)g_pAP[tid] + 1e-12f);
                s_rsold[tid] = rso;
                sd[tid] = 0.f;
            }
            __syncthreads();
            float alpha = s_a[c];
            float acc = 0.f;
            #pragma unroll
            for (int k = 0; k < 5; k++) {
                int i = gt + k * PTHREADS;
                if (i < NELEM) {
                    float p = g_P[i], ap = g_AP[i];
                    g_X[i] += alpha * p;
                    float r = g_R[i] - alpha * ap;
                    g_R[i] = r;
                    rc[k] = r; pc[k] = p;
                    acc += r * r;
                }
            }
            atomicAdd(&sd[c], acc);
            __syncthreads();
            if (tid < BB) atomicAdd(&g_RsB[tid], (double)sd[tid]);
        }
        grid_barrier(PBLOCKS);

        // ---- update2: beta; P = R + beta P; rotate scalars in block0
        {
            if (tid < BB) {
                double rsn = g_RsB[tid];
                s_a[tid] = (float)rsn / (s_rsold[tid] + 1e-12f);
                if (blockIdx.x == 0) {       // safe: nobody reads RsA/pAP this phase
                    g_RsA[tid] = rsn;
                    g_pAP[tid] = 0.0;
                }
            }
            __syncthreads();
            float beta = s_a[c];
            #pragma unroll
            for (int k = 0; k < 5; k++) {
                int i = gt + k * PTHREADS;
                if (i < NELEM) g_P[i] = rc[k] + beta * pc[k];
            }
            if (blockIdx.x == 0 && tid == 0) {
                int ok = 1;
                for (int q = 0; q < BB; q++)
                    if (g_RsB[q] >= TOL2) { ok = 0; break; }
                if (ok) g_done = 1;
            }
        }
        grid_barrier(PBLOCKS);
        if (*(volatile int*)&g_done) break;   // uniform across all blocks
    }

    // ===== epilogue: tiled transpose g_X (items x 64) -> out (64 x items) =====
    __shared__ float tile[32][65];
    for (int t = blockIdx.x; t < 512; t += PBLOCKS) {
        int it0 = t * 32;
        #pragma unroll
        for (int s = 0; s < 4; s++)
            tile[s * 8 + (tid >> 6)][tid & 63] =
                g_X[(it0 + s * 8 + (tid >> 6)) * BB + (tid & 63)];
        __syncthreads();
        #pragma unroll
        for (int s = 0; s < 4; s++)
            out[(s * 16 + (tid >> 5)) * NITEMS + it0 + (tid & 31)] =
                tile[tid & 31][s * 16 + (tid >> 5)];
        __syncthreads();
    }
}

// ---------------- launch: 4 graph nodes total ----------------
extern "C" void kernel_launch(void* const* d_in, const int* in_sizes, int n_in,
                              void* d_out, int out_size) {
    const float* Xb   = (const float*)d_in[0];
    const int*   rows = (const int*)d_in[1];
    const int*   cols = (const int*)d_in[2];
    const float* vals = (const float*)d_in[3];
    int nnz = in_sizes[1];
    if (nnz > MAXNNZ) nnz = MAXNNZ;

    const int HIST_BLOCKS = (nnz + 511) / 512;            // 2 nnz/thread
    const int PRE_BLOCKS  = 1024 + HIST_BLOCKS;

    k_pre    <<<PRE_BLOCKS, 256>>>(Xb, rows, cols, nnz);
    k_scan   <<<56, 1024>>>();
    k_scatter<<<HIST_BLOCKS, 256>>>(rows, cols, vals, nnz);
    k_cg     <<<PBLOCKS, 512>>>((float*)d_out);
}

// round 11
// speedup vs baseline: 1.9604x; 1.0216x over previous
#include <cuda_runtime.h>
#include <cuda_fp16.h>

#define NUSERS 40000
#define NITEMS 16384
#define MAXNNZ 1000000
#define BB 64
#define LAMBDA 500.0f
#define MAX_ITER 30
#define TOL2 1e-12   // TOL^2 vs Rs (sum of squares)

#define PBLOCKS 444                   // 148 SMs x 3 blocks of 512 threads
#define PTHREADS (PBLOCKS * 512)      // 227328
#define PWARPS   (PTHREADS / 32)      // 7104
#define NELEM    (NITEMS * BB)        // 1048576

// ---------------- device global scratch ----------------
__device__ int    g_row_cnt[NUSERS];
__device__ int    g_row_ptr[NUSERS + 1];
__device__ int    g_row_off[NUSERS];
__device__ int    g_col_cnt[NITEMS];
__device__ int    g_col_ptr[NITEMS + 1];
__device__ int    g_col_off[NITEMS];
__device__ __align__(16) int2 g_csr[MAXNNZ];   // {col, float_bits(val)}
__device__ __align__(16) int2 g_csc[MAXNNZ];   // {row, float_bits(val)}
__device__ int    g_bsum[64];

__device__ float   g_tmp  [NUSERS * BB];       // fp32 tmp (RHS pass only)
__device__ __half2 g_tmp16[NUSERS * (BB / 2)]; // fp16 tmp (CG iterations)
__device__ float  g_Xt [NELEM];
__device__ float  g_X  [NELEM];
__device__ float  g_R  [NELEM];
__device__ float  g_P  [NELEM];
__device__ float  g_AP [NELEM];

__device__ double g_RsA[BB];   // Rs_old
__device__ double g_RsB[BB];   // Rs_new
__device__ double g_pAP[BB];
__device__ int    g_done;

// ---------------- grid-wide barrier (sense via generation counter) ----------------
__device__ unsigned g_bar_cnt;
__device__ unsigned g_bar_gen;

__device__ __forceinline__ void grid_barrier(unsigned nblocks) {
    __syncthreads();
    if (threadIdx.x == 0) {
        unsigned gen = *(volatile unsigned*)&g_bar_gen;
        __threadfence();
        if (atomicAdd(&g_bar_cnt, 1u) == nblocks - 1u) {
            g_bar_cnt = 0u;
            __threadfence();
            atomicAdd(&g_bar_gen, 1u);
        } else {
            while (*(volatile unsigned*)&g_bar_gen == gen) { }
        }
        __threadfence();
    }
    __syncthreads();
}

// ---------------- fp32 row gather with cooperative smem idx staging (R10-proven) ----------------
__device__ __forceinline__ float2 row_gather(const int2* __restrict__ idx,
                                             const float* __restrict__ V,
                                             int s, int e, int lane,
                                             int2* __restrict__ sbuf) {
    float2 a0 = {0.f,0.f}, a1 = {0.f,0.f}, a2 = {0.f,0.f}, a3 = {0.f,0.f};
    for (int base = s; base < e; base += 32) {
        int n = e - base; if (n > 32) n = 32;
        if (lane < n) sbuf[lane] = __ldcs(idx + base + lane);
        __syncwarp();
        int k = 0;
        for (; k + 3 < n; k += 4) {
            int2 p0 = sbuf[k],     p1 = sbuf[k + 1];
            int2 p2 = sbuf[k + 2], p3 = sbuf[k + 3];
            float2 q0 = *(const float2*)(V + p0.x * BB + 2 * lane);
            float2 q1 = *(const float2*)(V + p1.x * BB + 2 * lane);
            float2 q2 = *(const float2*)(V + p2.x * BB + 2 * lane);
            float2 q3 = *(const float2*)(V + p3.x * BB + 2 * lane);
            float v0 = __int_as_float(p0.y), v1 = __int_as_float(p1.y);
            float v2 = __int_as_float(p2.y), v3 = __int_as_float(p3.y);
            a0.x += v0*q0.x; a0.y += v0*q0.y;
            a1.x += v1*q1.x; a1.y += v1*q1.y;
            a2.x += v2*q2.x; a2.y += v2*q2.y;
            a3.x += v3*q3.x; a3.y += v3*q3.y;
        }
        for (; k < n; k++) {
            int2 p = sbuf[k];
            float2 q = *(const float2*)(V + p.x * BB + 2 * lane);
            float v = __int_as_float(p.y);
            a0.x += v*q.x; a0.y += v*q.y;
        }
        __syncwarp();
    }
    return make_float2((a0.x + a1.x) + (a2.x + a3.x),
                       (a0.y + a1.y) + (a2.y + a3.y));
}

// ---------------- fp16-operand row gather: 128B rows -> 1 wavefront per nnz ----------------
__device__ __forceinline__ float2 row_gather16(const int2* __restrict__ idx,
                                               const __half2* __restrict__ V,
                                               int s, int e, int lane,
                                               int2* __restrict__ sbuf) {
    float2 a0 = {0.f,0.f}, a1 = {0.f,0.f}, a2 = {0.f,0.f}, a3 = {0.f,0.f};
    for (int base = s; base < e; base += 32) {
        int n = e - base; if (n > 32) n = 32;
        if (lane < n) sbuf[lane] = __ldcs(idx + base + lane);
        __syncwarp();
        int k = 0;
        for (; k + 3 < n; k += 4) {
            int2 p0 = sbuf[k],     p1 = sbuf[k + 1];
            int2 p2 = sbuf[k + 2], p3 = sbuf[k + 3];
            float2 q0 = __half22float2(V[p0.x * (BB/2) + lane]);
            float2 q1 = __half22float2(V[p1.x * (BB/2) + lane]);
            float2 q2 = __half22float2(V[p2.x * (BB/2) + lane]);
            float2 q3 = __half22float2(V[p3.x * (BB/2) + lane]);
            float v0 = __int_as_float(p0.y), v1 = __int_as_float(p1.y);
            float v2 = __int_as_float(p2.y), v3 = __int_as_float(p3.y);
            a0.x += v0*q0.x; a0.y += v0*q0.y;
            a1.x += v1*q1.x; a1.y += v1*q1.y;
            a2.x += v2*q2.x; a2.y += v2*q2.y;
            a3.x += v3*q3.x; a3.y += v3*q3.y;
        }
        for (; k < n; k++) {
            int2 p = sbuf[k];
            float2 q = __half22float2(V[p.x * (BB/2) + lane]);
            float v = __int_as_float(p.y);
            a0.x += v*q.x; a0.y += v*q.y;
        }
        __syncwarp();
    }
    return make_float2((a0.x + a1.x) + (a2.x + a3.x),
                       (a0.y + a1.y) + (a2.y + a3.y));
}

// ---------------- k_pre: tiled transpose + X zero + histogram + scalar zero ----------------
__global__ void k_pre(const float* __restrict__ Xb, const int* __restrict__ rows,
                      const int* __restrict__ cols, int nnz) {
    int b = blockIdx.x;
    if (b < 1024) {
        __shared__ float tile[32][33];
        int itile = (b & 511) * 32;
        int btile = (b >> 9) * 32;
        int tx = threadIdx.x & 31;
        int ty = threadIdx.x >> 5;               // 0..7
        #pragma unroll
        for (int r = 0; r < 32; r += 8)          // coalesced read along item
            tile[ty + r][tx] = __ldg(&Xb[(btile + ty + r) * NITEMS + itile + tx]);
        __syncthreads();
        #pragma unroll
        for (int r = 0; r < 32; r += 8) {
            int item = itile + ty + r;
            g_Xt[item * BB + btile + tx] = tile[tx][ty + r];
            g_X [item * BB + btile + tx] = 0.0f;
        }
        if (b == 0) {
            if (threadIdx.x < BB) {
                g_RsA[threadIdx.x] = 0.0; g_RsB[threadIdx.x] = 0.0;
                g_pAP[threadIdx.x] = 0.0;
            }
            if (threadIdx.x == 64) g_done = 0;
        }
    } else {
        int k2 = ((b - 1024) * 256 + threadIdx.x) * 2;
        if (k2 + 1 < nnz) {
            int2 r = *(const int2*)(rows + k2);
            int2 c = *(const int2*)(cols + k2);
            atomicAdd(&g_row_cnt[r.x], 1); atomicAdd(&g_row_cnt[r.y], 1);
            atomicAdd(&g_col_cnt[c.x], 1); atomicAdd(&g_col_cnt[c.y], 1);
        } else {
            for (int k = k2; k < nnz; k++) {
                atomicAdd(&g_row_cnt[__ldg(rows + k)], 1);
                atomicAdd(&g_col_cnt[__ldg(cols + k)], 1);
            }
        }
    }
}

// ---------------- fused hierarchical scan (56 resident blocks), self-cleaning ----------------
__global__ void k_scan() {
    __shared__ int wsum[32];
    int b = blockIdx.x;
    bool isRow = (b < 40);
    int* cnt = isRow ? g_row_cnt : g_col_cnt;
    int* ptr = isRow ? g_row_ptr : g_col_ptr;
    int* off = isRow ? g_row_off : g_col_off;
    int n    = isRow ? NUSERS    : NITEMS;
    int i = (isRow ? b : (b - 40)) * 1024 + threadIdx.x;
    int lane = threadIdx.x & 31, w = threadIdx.x >> 5;

    int v = 0;
    if (i < n) { v = cnt[i]; cnt[i] = 0; }   // consume + clean for next replay
    int x = v;
    #pragma unroll
    for (int s = 1; s < 32; s <<= 1) {
        int t = __shfl_up_sync(0xffffffffu, x, s);
        if (lane >= s) x += t;
    }
    if (lane == 31) wsum[w] = x;
    __syncthreads();
    if (w == 0) {
        int y = wsum[lane];
        #pragma unroll
        for (int s = 1; s < 32; s <<= 1) {
            int t = __shfl_up_sync(0xffffffffu, y, s);
            if (lane >= s) y += t;
        }
        wsum[lane] = y;
    }
    __syncthreads();
    int incl = x + (w ? wsum[w - 1] : 0);
    int loc_excl = incl - v;
    if (threadIdx.x == 1023) g_bsum[b] = incl;

    grid_barrier(56);

    if (b == 0 && threadIdx.x == 0) {
        int s = 0;
        for (int k = 0; k < 40; k++) { int t = g_bsum[k]; g_bsum[k] = s; s += t; }
        g_row_ptr[NUSERS] = s;
    }
    if (b == 1 && threadIdx.x == 0) {
        int s = 0;
        for (int k = 40; k < 56; k++) { int t = g_bsum[k]; g_bsum[k] = s; s += t; }
        g_col_ptr[NITEMS] = s;
    }

    grid_barrier(56);

    if (i < n) {
        int p = loc_excl + g_bsum[b];
        ptr[i] = p;
        off[i] = p;
    }
}

// ---------------- scatter: 2 nnz per thread, full-width grid ----------------
__global__ void k_scatter(const int* __restrict__ rows, const int* __restrict__ cols,
                          const float* __restrict__ vals, int nnz) {
    int k2 = (blockIdx.x * blockDim.x + threadIdx.x) * 2;
    if (k2 + 1 < nnz) {
        int2   r = *(const int2*)(rows + k2);
        int2   c = *(const int2*)(cols + k2);
        float2 v = *(const float2*)(vals + k2);
        int p0 = atomicAdd(&g_row_off[r.x], 1);
        int p1 = atomicAdd(&g_row_off[r.y], 1);
        g_csr[p0] = make_int2(c.x, __float_as_int(v.x));
        g_csr[p1] = make_int2(c.y, __float_as_int(v.y));
        int q0 = atomicAdd(&g_col_off[c.x], 1);
        int q1 = atomicAdd(&g_col_off[c.y], 1);
        g_csc[q0] = make_int2(r.x, __float_as_int(v.x));
        g_csc[q1] = make_int2(r.y, __float_as_int(v.y));
    } else {
        for (int k = k2; k < nnz; k++) {
            int rr = __ldg(rows + k); int cc = __ldg(cols + k);
            int vb = __float_as_int(__ldg(vals + k));
            int p = atomicAdd(&g_row_off[rr], 1);
            g_csr[p] = make_int2(cc, vb);
            int q = atomicAdd(&g_col_off[cc], 1);
            g_csc[q] = make_int2(rr, vb);
        }
    }
}

// ---------------- persistent CG mega-kernel (R10 core; fp16 tmp in iterations) ----------------
__global__ void __launch_bounds__(512, 3) k_cg(float* __restrict__ out) {
    __shared__ float sd[BB];
    __shared__ float s_a[BB];        // alpha, then beta
    __shared__ float s_rsold[BB];
    __shared__ int2  s_idx[16][32];  // per-warp idx staging (4KB)

    int tid  = threadIdx.x;
    int gt   = blockIdx.x * 512 + tid;
    int gw   = gt >> 5;
    int lane = tid & 31;
    int c0   = 2 * lane;
    int c    = tid & 63;   // PTHREADS % 64 == 0 -> column fixed per thread
    int2* sbuf = s_idx[tid >> 5];

    // ===== RHS csr: tmp = X @ Xt (PURE FP32 — RHS must not carry fp16 bias) =====
    for (int row = gw; row < NUSERS; row += PWARPS) {
        float2 o = row_gather(g_csr, g_Xt, g_row_ptr[row], g_row_ptr[row + 1], lane, sbuf);
        *(float2*)(g_tmp + row * BB + c0) = o;
    }
    grid_barrier(PBLOCKS);

    // ===== RHS csc: R0 = P0 = X^T tmp ; RsA = ||R0||^2 (fp32) =====
    if (tid < BB) sd[tid] = 0.f;
    __syncthreads();
    {
        float ax = 0.f, ay = 0.f;
        for (int row = gw; row < NITEMS; row += PWARPS) {
            float2 o = row_gather(g_csc, g_tmp, g_col_ptr[row], g_col_ptr[row + 1], lane, sbuf);
            *(float2*)(g_R + row * BB + c0) = o;
            *(float2*)(g_P + row * BB + c0) = o;
            ax += o.x * o.x; ay += o.y * o.y;
        }
        atomicAdd(&sd[c0], ax); atomicAdd(&sd[c0 + 1], ay);
        __syncthreads();
        if (tid < BB) atomicAdd(&g_RsA[tid], (double)sd[tid]);
    }
    grid_barrier(PBLOCKS);

    // ===== 30 CG iterations (4 barriers, explicit RsB reduction; fp16 tmp) =====
    for (int it = 0; it < MAX_ITER; it++) {
        // ---- csr: tmp16 = X @ P (fp32 math, fp16 store) ; block0 zeroes RsB
        if (blockIdx.x == 0 && tid < BB) g_RsB[tid] = 0.0;
        for (int row = gw; row < NUSERS; row += PWARPS) {
            float2 o = row_gather(g_csr, g_P, g_row_ptr[row], g_row_ptr[row + 1], lane, sbuf);
            g_tmp16[row * (BB/2) + lane] = __floats2half2_rn(o.x, o.y);
        }
        grid_barrier(PBLOCKS);

        // ---- csc: AP = X^T tmp16 + lambda P ; pAP += P.AP
        if (tid < BB) sd[tid] = 0.f;
        __syncthreads();
        {
            float ax = 0.f, ay = 0.f;
            for (int row = gw; row < NITEMS; row += PWARPS) {
                float2 o = row_gather16(g_csc, g_tmp16, g_col_ptr[row], g_col_ptr[row + 1], lane, sbuf);
                float2 p = *(const float2*)(g_P + row * BB + c0);
                o.x += LAMBDA * p.x; o.y += LAMBDA * p.y;
                *(float2*)(g_AP + row * BB + c0) = o;
                ax += p.x * o.x; ay += p.y * o.y;
            }
            atomicAdd(&sd[c0], ax); atomicAdd(&sd[c0 + 1], ay);
            __syncthreads();
            if (tid < BB) atomicAdd(&g_pAP[tid], (double)sd[tid]);
        }
        grid_barrier(PBLOCKS);

        // ---- update1: alpha; X += aP; R -= a AP; RsB = sum(R^2)
        float rc[5], pc[5];
        {
            if (tid < BB) {
                float rso = (float)g_RsA[tid];
                s_a[tid] = rso / ((float)g_pAP[tid] + 1e-12f);
                s_rsold[tid] = rso;
                sd[tid] = 0.f;
            }
            __syncthreads();
            float alpha = s_a[c];
            float acc = 0.f;
            #pragma unroll
            for (int k = 0; k < 5; k++) {
                int i = gt + k * PTHREADS;
                if (i < NELEM) {
                    float p = g_P[i], ap = g_AP[i];
                    g_X[i] += alpha * p;
                    float r = g_R[i] - alpha * ap;
                    g_R[i] = r;
                    rc[k] = r; pc[k] = p;
                    acc += r * r;
                }
            }
            atomicAdd(&sd[c], acc);
            __syncthreads();
            if (tid < BB) atomicAdd(&g_RsB[tid], (double)sd[tid]);
        }
        grid_barrier(PBLOCKS);

        // ---- update2: beta; P = R + beta P; rotate scalars in block0
        {
            if (tid < BB) {
                double rsn = g_RsB[tid];
                s_a[tid] = (float)rsn / (s_rsold[tid] + 1e-12f);
                if (blockIdx.x == 0) {       // safe: nobody reads RsA/pAP this phase
                    g_RsA[tid] = rsn;
                    g_pAP[tid] = 0.0;
                }
            }
            __syncthreads();
            float beta = s_a[c];
            #pragma unroll
            for (int k = 0; k < 5; k++) {
                int i = gt + k * PTHREADS;
                if (i < NELEM) g_P[i] = rc[k] + beta * pc[k];
            }
            if (blockIdx.x == 0 && tid == 0) {
                int ok = 1;
                for (int q = 0; q < BB; q++)
                    if (g_RsB[q] >= TOL2) { ok = 0; break; }
                if (ok) g_done = 1;
            }
        }
        grid_barrier(PBLOCKS);
        if (*(volatile int*)&g_done) break;   // uniform across all blocks
    }

    // ===== epilogue: tiled transpose g_X (items x 64) -> out (64 x items) =====
    __shared__ float tile[32][65];
    for (int t = blockIdx.x; t < 512; t += PBLOCKS) {
        int it0 = t * 32;
        #pragma unroll
        for (int s = 0; s < 4; s++)
            tile[s * 8 + (tid >> 6)][tid & 63] =
                g_X[(it0 + s * 8 + (tid >> 6)) * BB + (tid & 63)];
        __syncthreads();
        #pragma unroll
        for (int s = 0; s < 4; s++)
            out[(s * 16 + (tid >> 5)) * NITEMS + it0 + (tid & 31)] =
                tile[tid & 31][s * 16 + (tid >> 5)];
        __syncthreads();
    }
}

// ---------------- launch: 4 graph nodes total ----------------
extern "C" void kernel_launch(void* const* d_in, const int* in_sizes, int n_in,
                              void* d_out, int out_size) {
    const float* Xb   = (const float*)d_in[0];
    const int*   rows = (const int*)d_in[1];
    const int*   cols = (const int*)d_in[2];
    const float* vals = (const float*)d_in[3];
    int nnz = in_sizes[1];
    if (nnz > MAXNNZ) nnz = MAXNNZ;

    const int HIST_BLOCKS = (nnz + 511) / 512;            // 2 nnz/thread
    const int PRE_BLOCKS  = 1024 + HIST_BLOCKS;

    k_pre    <<<PRE_BLOCKS, 256>>>(Xb, rows, cols, nnz);
    k_scan   <<<56, 1024>>>();
    k_scatter<<<HIST_BLOCKS, 256>>>(rows, cols, vals, nnz);
    k_cg     <<<PBLOCKS, 512>>>((float*)d_out);
}